// round 9
// baseline (speedup 1.0000x reference)
#include <cuda_runtime.h>
#include <cuda_bf16.h>
#include <stdint.h>

// ===========================================================================
// GenNCA via mma.sync.m16n8k16 bf16 (sm_80 PTX -> legal on plain sm_100).
// conv0|conv1|fc0 folded into one 3x3 conv 32->128 (M); relu; fc1; mask; +x.
// Operands split hi/lo bf16 (3 mma terms ~= 17-bit mantissa); fp32 master state.
// R9: 512 threads (16 warps, 4/SMSP) + unrolled tap loop for latency coverage.
// ===========================================================================
#define STEPS_ 64
#define PLANE_ (8 * 32 * 128 * 128)
#define NT_ 512

__device__ float    g_xf[2][PLANE_];          // fp32 master state, NHWC
__device__ unsigned short g_xq[2][PLANE_ * 2];// operand planes [px][hi32|lo32] bf16
__device__ float    g_Mf[288 * 128];          // folded weights [k][hid]
__device__ unsigned short g_B1h[128 * 296];   // hi  [n=hid][k=288 +pad]
__device__ uint2    g_B1l[18 * 16 * 32];      // lo fragments [kk][ntile][lane]
__device__ unsigned short g_B2h[32 * 136];    // fc1 hi [o][h +pad]
__device__ unsigned short g_B2l[32 * 136];    // fc1 lo
__device__ float    g_bp[128];
__device__ unsigned g_keys[2 * STEPS_];

// ---- smem byte offsets ----
#define SA_    0          // 3 slots x (hi 130*80 + lo 130*80)
#define SLOT_  20800
#define SALO_  10400
#define SB1_   62400      // 128 x 592
#define SB2H_  138176     // 32 x 272
#define SB2L_  146880
#define SHHI_  155584     // 128 x 272
#define SHLO_  190400
#define SBIAS_ 225216
#define SMASK_ 225728
#define SMEM_BYTES 226240

// ---------------------------------------------------------------------------
__device__ __forceinline__ uint32_t smem_u32(const void* p) {
    uint32_t a;
    asm("{ .reg .u64 t; cvta.to.shared.u64 t, %1; cvt.u32.u64 %0, t; }" : "=r"(a) : "l"(p));
    return a;
}
__device__ __forceinline__ void cp16(uint32_t dst, const void* src) {
    asm volatile("cp.async.cg.shared.global [%0], [%1], 16;" :: "r"(dst), "l"(src) : "memory");
}
#define CP_COMMIT() asm volatile("cp.async.commit_group;" ::: "memory")
#define CP_WAIT0()  asm volatile("cp.async.wait_group 0;" ::: "memory")
__device__ __forceinline__ void ldm4(uint32_t* d, uint32_t a) {
    asm volatile("ldmatrix.sync.aligned.m8n8.x4.shared.b16 {%0,%1,%2,%3}, [%4];"
                 : "=r"(d[0]), "=r"(d[1]), "=r"(d[2]), "=r"(d[3]) : "r"(a));
}
__device__ __forceinline__ void mmabf(float* c, const uint32_t* a, uint32_t b0, uint32_t b1) {
    asm volatile("mma.sync.aligned.m16n8k16.row.col.f32.bf16.bf16.f32 "
                 "{%0,%1,%2,%3}, {%4,%5,%6,%7}, {%8,%9}, {%0,%1,%2,%3};"
                 : "+f"(c[0]), "+f"(c[1]), "+f"(c[2]), "+f"(c[3])
                 : "r"(a[0]), "r"(a[1]), "r"(a[2]), "r"(a[3]), "r"(b0), "r"(b1));
}
__device__ __forceinline__ unsigned short bfhi(float v) {
    return __bfloat16_as_ushort(__float2bfloat16(v));
}
__device__ __forceinline__ unsigned short bflo(float v) {
    float h = __bfloat162float(__float2bfloat16(v));
    return __bfloat16_as_ushort(__float2bfloat16(v - h));
}
__device__ __forceinline__ uint32_t pack2(unsigned short a, unsigned short b) {
    return (uint32_t)a | ((uint32_t)b << 16);
}

// ---------------------------------------------------------------------------
__device__ __forceinline__ void threefry2x32(unsigned k0, unsigned k1,
                                             unsigned x0, unsigned x1,
                                             unsigned& o0, unsigned& o1) {
    unsigned ks2 = k0 ^ k1 ^ 0x1BD11BDAu;
#define TFR(r) { x0 += x1; x1 = __funnelshift_l(x1, x1, (r)); x1 ^= x0; }
    x0 += k0; x1 += k1;
    TFR(13) TFR(15) TFR(26) TFR(6)  x0 += k1;  x1 += ks2 + 1u;
    TFR(17) TFR(29) TFR(16) TFR(24) x0 += ks2; x1 += k0 + 2u;
    TFR(13) TFR(15) TFR(26) TFR(6)  x0 += k0;  x1 += k1 + 3u;
    TFR(17) TFR(29) TFR(16) TFR(24) x0 += k1;  x1 += ks2 + 4u;
    TFR(13) TFR(15) TFR(26) TFR(6)  x0 += ks2; x1 += k0 + 5u;
#undef TFR
    o0 = x0; o1 = x1;
}
__device__ __forceinline__ float mask_for(unsigned k0, unsigned k1, unsigned idx) {
    unsigned o0, o1;
    threefry2x32(k0, k1, 0u, idx, o0, o1);
    unsigned bits = o0 ^ o1;
    float u = __uint_as_float((bits >> 9) | 0x3f800000u) - 1.0f;
    return (u > 0.5f) ? 1.0f : 0.0f;
}

// ---------------------------------------------------------------------------
__global__ void prep1(const float* __restrict__ fc0w, const float* __restrict__ fc0b,
                      const float* __restrict__ p0w, const float* __restrict__ p0b,
                      const float* __restrict__ p1w, const float* __restrict__ p1b) {
    int bid = blockIdx.x, h = threadIdx.x;
    if (bid < 288) {
        int tap = bid >> 5, c = bid & 31;
        float acc = (tap == 4) ? fc0w[h * 96 + c] : 0.0f;
        const float* w0 = &p0w[bid * 32];
        const float* w1 = &p1w[bid * 32];
        const float* f1 = &fc0w[h * 96 + 32];
        const float* f2 = &fc0w[h * 96 + 64];
#pragma unroll
        for (int o = 0; o < 32; o++) acc += w0[o] * f1[o] + w1[o] * f2[o];
        g_Mf[bid * 128 + h] = acc;
    } else {
        float acc = fc0b[h];
        const float* f1 = &fc0w[h * 96 + 32];
        const float* f2 = &fc0w[h * 96 + 64];
#pragma unroll
        for (int o = 0; o < 32; o++) acc += p0b[o] * f1[o] + p1b[o] * f2[o];
        g_bp[h] = acc;
        if (h == 0)
            for (unsigned s = 0; s < STEPS_; s++) {
                unsigned a, b;
                threefry2x32(0u, 42u, 0u, s, a, b);
                g_keys[2 * s] = a; g_keys[2 * s + 1] = b;
            }
    }
}

__global__ void prep2(const float* __restrict__ fc1w) {
    int tid = blockIdx.x * 256 + threadIdx.x;
    if (tid < 36864) {                 // B1 hi: [n][k]
        int n = tid / 288, k = tid % 288;
        g_B1h[n * 296 + k] = bfhi(g_Mf[k * 128 + n]);
    } else if (tid < 46080) {          // B1 lo fragments
        int j = tid - 36864;
        int l = j & 31, ntile = (j >> 5) & 15, kk = j >> 9;
        int n = ntile * 8 + (l >> 2), k0 = kk * 16 + 2 * (l & 3);
        g_B1l[j] = make_uint2(
            pack2(bflo(g_Mf[k0 * 128 + n]),       bflo(g_Mf[(k0 + 1) * 128 + n])),
            pack2(bflo(g_Mf[(k0 + 8) * 128 + n]), bflo(g_Mf[(k0 + 9) * 128 + n])));
    } else if (tid < 50176) {          // B2: [o][h]
        int j = tid - 46080;
        int o = j >> 7, h = j & 127;
        float v = fc1w[j];
        g_B2h[o * 136 + h] = bfhi(v);
        g_B2l[o * 136 + h] = bflo(v);
    }
}

__global__ void init_state(const float* __restrict__ x, const float* __restrict__ xvec,
                           const float* __restrict__ bptw, const float* __restrict__ bptb) {
    int tid = blockIdx.x * blockDim.x + threadIdx.x;
    if (tid >= PLANE_) return;
    int c = tid & 31, b = tid >> 19;
    float v;
    if (c >= 26) {
        int e = c - 26;
        v = bptw[b * 6 + e] * xvec[b * 6 + e] + bptb[b * 6 + e];
    } else v = x[tid];
    g_xf[0][tid] = v;
    int p = tid >> 5;
    g_xq[0][p * 64 + c] = bfhi(v);
    g_xq[0][p * 64 + 32 + c] = bflo(v);
}

__global__ void final_out(float* __restrict__ out) {
    int tid = blockIdx.x * blockDim.x + threadIdx.x;
    if (tid >= PLANE_) return;
    out[tid] = g_xf[0][tid];
}

// ---------------------------------------------------------------------------
// Step kernel: block = (row-group of 8, batch), 512 threads (16 warps).
// GEMM1: mg=wid>>2 (0..3) -> 32px, ng=wid&3 -> 32hid.
// GEMM2: mg2=wid>>1 (0..7) -> 16px, ng2=wid&1 -> 16out.
// ---------------------------------------------------------------------------
__global__ void __launch_bounds__(NT_, 1) nca_step(int s) {
    extern __shared__ char smem[];
    const uint32_t sb = smem_u32(smem);
    float* sbias = (float*)(smem + SBIAS_);
    float* smask = (float*)(smem + SMASK_);

    const int t = threadIdx.x, l = t & 31, wid = t >> 5;
    const int b = blockIdx.y, r0 = blockIdx.x * 8;
    const int mg = wid >> 2, ng = wid & 3;
    const int mg2 = wid >> 1, ng2 = wid & 1;

    const unsigned short* __restrict__ xq_in = g_xq[s & 1];
    unsigned short*       __restrict__ xq_out = g_xq[(s & 1) ^ 1];
    const float* __restrict__ xf_in = g_xf[s & 1];
    float*       __restrict__ xf_out = g_xf[(s & 1) ^ 1];

    // resident weights
    for (int u = t; u < 4736; u += NT_) cp16(sb + SB1_ + u * 16, (const char*)g_B1h + u * 16);
    for (int u = t; u < 544; u += NT_)  cp16(sb + SB2H_ + u * 16, (const char*)g_B2h + u * 16);
    for (int u = t; u < 544; u += NT_)  cp16(sb + SB2L_ + u * 16, (const char*)g_B2l + u * 16);
    CP_COMMIT();
    if (t < 128) sbias[t] = g_bp[t];

    auto load_row = [&](int r) {
        int slot = (r + 3) % 3;
        int src = r < 0 ? 1 : (r > 127 ? 126 : r);
        const char* base = (const char*)xq_in + (size_t)(((b << 7) + src) << 7) * 128;
        uint32_t d0 = sb + SA_ + (uint32_t)slot * SLOT_;
        for (int u = t; u < 1040; u += NT_) {
            int p, sp, c8;
            if (u < 1024)      { p = (u >> 3) + 1; sp = u >> 3; c8 = u & 7; }
            else if (u < 1032) { p = 0;   sp = 1;   c8 = u - 1024; }
            else               { p = 129; sp = 126; c8 = u - 1032; }
            uint32_t dst = d0 + (uint32_t)p * 80 +
                           (c8 < 4 ? (uint32_t)c8 * 16 : SALO_ + (uint32_t)(c8 - 4) * 16);
            cp16(dst, base + sp * 128 + c8 * 16);
        }
        CP_COMMIT();
    };
    load_row(r0 - 1); load_row(r0); load_row(r0 + 1);

    const unsigned key0 = g_keys[2 * s], key1 = g_keys[2 * s + 1];
    const uint32_t aoff  = (uint32_t)(l & 15) * 80 + (uint32_t)(l >> 4) * 16;
    const uint32_t b1off = sb + SB1_ + (uint32_t)(ng * 32 + ((l >> 4) << 3) + (l & 7)) * 592
                         + (uint32_t)((l >> 3) & 1) * 16;
    const uint32_t hoff  = sb + SHHI_ + (uint32_t)(mg2 * 16 + (l & 15)) * 272 + (uint32_t)(l >> 4) * 16;
    const uint32_t b2off = sb + SB2H_ + (uint32_t)(ng2 * 16 + ((l >> 4) << 3) + (l & 7)) * 272
                         + (uint32_t)((l >> 3) & 1) * 16;

    for (int r = r0; r < r0 + 8; r++) {
        CP_WAIT0();
        __syncthreads();
        if (t < 128) smask[t] = mask_for(key0, key1, (unsigned)((((b << 7) + r) << 7) + t));

        // ================= GEMM1: 128px x 128hid, K=288 =================
        float c1[2][4][4];
#pragma unroll
        for (int mt = 0; mt < 2; mt++)
#pragma unroll
            for (int nt = 0; nt < 4; nt++)
#pragma unroll
                for (int i = 0; i < 4; i++) c1[mt][nt][i] = 0.0f;

#pragma unroll 1
        for (int dy = 0; dy < 3; dy++) {
            uint32_t slotb = sb + SA_ + (uint32_t)((r - 1 + dy + 3) % 3) * SLOT_;
#pragma unroll
            for (int dx = 0; dx < 3; dx++) {
                uint32_t abase = slotb + (uint32_t)(mg * 32 + dx) * 80 + aoff;
                int tap2 = (dy * 3 + dx) * 2;
#pragma unroll
                for (int k2 = 0; k2 < 2; k2++) {
                    int kk = tap2 + k2;
                    uint32_t ah[2][4], al[2][4], bh[2][4];
                    uint2 bl[4];
#pragma unroll
                    for (int mt = 0; mt < 2; mt++) {
                        ldm4(ah[mt], abase + (uint32_t)mt * 1280 + (uint32_t)k2 * 32);
                        ldm4(al[mt], abase + SALO_ + (uint32_t)mt * 1280 + (uint32_t)k2 * 32);
                    }
                    ldm4(bh[0], b1off + (uint32_t)kk * 32);
                    ldm4(bh[1], b1off + 16 * 592 + (uint32_t)kk * 32);
#pragma unroll
                    for (int nt = 0; nt < 4; nt++)
                        bl[nt] = __ldg(&g_B1l[(kk * 16 + ng * 4 + nt) * 32 + l]);
                    // term1: hi*hi
#pragma unroll
                    for (int mt = 0; mt < 2; mt++)
#pragma unroll
                        for (int nt = 0; nt < 4; nt++)
                            mmabf(c1[mt][nt], ah[mt], bh[nt >> 1][(nt & 1) * 2], bh[nt >> 1][(nt & 1) * 2 + 1]);
                    // term2: lo_a*hi_b
#pragma unroll
                    for (int mt = 0; mt < 2; mt++)
#pragma unroll
                        for (int nt = 0; nt < 4; nt++)
                            mmabf(c1[mt][nt], al[mt], bh[nt >> 1][(nt & 1) * 2], bh[nt >> 1][(nt & 1) * 2 + 1]);
                    // term3: hi_a*lo_b
#pragma unroll
                    for (int mt = 0; mt < 2; mt++)
#pragma unroll
                        for (int nt = 0; nt < 4; nt++)
                            mmabf(c1[mt][nt], ah[mt], bl[nt].x, bl[nt].y);
                }
            }
        }
        __syncthreads();                 // sA slot (r-1) free; smask visible
        if (r < r0 + 7) load_row(r + 2);

        // ---- epilogue1: bias+relu, split -> sH hi/lo ----
#pragma unroll
        for (int mt = 0; mt < 2; mt++) {
            int px = mg * 32 + mt * 16 + (l >> 2);
#pragma unroll
            for (int nt = 0; nt < 4; nt++) {
                int o = ng * 32 + nt * 8 + ((l & 3) << 1);
                float b0 = sbias[o], b1 = sbias[o + 1];
                float v0 = fmaxf(c1[mt][nt][0] + b0, 0.f), v1 = fmaxf(c1[mt][nt][1] + b1, 0.f);
                float v2 = fmaxf(c1[mt][nt][2] + b0, 0.f), v3 = fmaxf(c1[mt][nt][3] + b1, 0.f);
                *(uint32_t*)(smem + SHHI_ + px * 272 + o * 2) = pack2(bfhi(v0), bfhi(v1));
                *(uint32_t*)(smem + SHHI_ + (px + 8) * 272 + o * 2) = pack2(bfhi(v2), bfhi(v3));
                *(uint32_t*)(smem + SHLO_ + px * 272 + o * 2) = pack2(bflo(v0), bflo(v1));
                *(uint32_t*)(smem + SHLO_ + (px + 8) * 272 + o * 2) = pack2(bflo(v2), bflo(v3));
            }
        }
        __syncthreads();                 // sH ready

        // ================= GEMM2: 128px x 32out, K=128 =================
        float c2[2][4];
#pragma unroll
        for (int nt = 0; nt < 2; nt++)
#pragma unroll
            for (int i = 0; i < 4; i++) c2[nt][i] = 0.0f;
#pragma unroll
        for (int kk = 0; kk < 8; kk++) {
            uint32_t ah[4], al[4], bh[4], blr[4];
            ldm4(ah, hoff + (uint32_t)kk * 32);
            ldm4(al, hoff + (SHLO_ - SHHI_) + (uint32_t)kk * 32);
            ldm4(bh, b2off + (uint32_t)kk * 32);
            ldm4(blr, b2off + (SB2L_ - SB2H_) + (uint32_t)kk * 32);
#pragma unroll
            for (int nt = 0; nt < 2; nt++) {
                mmabf(c2[nt], ah, bh[nt * 2], bh[nt * 2 + 1]);
                mmabf(c2[nt], al, bh[nt * 2], bh[nt * 2 + 1]);
                mmabf(c2[nt], ah, blr[nt * 2], blr[nt * 2 + 1]);
            }
        }

        // ---- epilogue2: residual (fp32 master) + mask, write state ----
        {
            int px = mg2 * 16 + (l >> 2);
            float m0 = smask[px], m1 = smask[px + 8];
            uint32_t pbase = (uint32_t)(((((b << 7) + r) << 7) + px) << 5);
#pragma unroll
            for (int nt = 0; nt < 2; nt++) {
                int o = ng2 * 16 + nt * 8 + ((l & 3) << 1);
                float2 x0 = *(const float2*)&xf_in[pbase + o];
                float2 x1 = *(const float2*)&xf_in[pbase + 256 + o];
                float n0 = x0.x + c2[nt][0] * m0;
                float n1 = x0.y + c2[nt][1] * m0;
                float n2 = x1.x + c2[nt][2] * m1;
                float n3 = x1.y + c2[nt][3] * m1;
                *(float2*)&xf_out[pbase + o] = make_float2(n0, n1);
                *(float2*)&xf_out[pbase + 256 + o] = make_float2(n2, n3);
                uint32_t gi = pbase + (uint32_t)(o >> 1);   // uint32 units: 32/pixel
                ((uint32_t*)xq_out)[gi]            = pack2(bfhi(n0), bfhi(n1));
                ((uint32_t*)xq_out)[gi + 16]       = pack2(bflo(n0), bflo(n1));
                ((uint32_t*)xq_out)[gi + 256]      = pack2(bfhi(n2), bfhi(n3));
                ((uint32_t*)xq_out)[gi + 256 + 16] = pack2(bflo(n2), bflo(n3));
            }
        }
    }
}

// ---------------------------------------------------------------------------
extern "C" void kernel_launch(void* const* d_in, const int* in_sizes, int n_in,
                              void* d_out, int out_size) {
    const float* x    = (const float*)d_in[0];
    const float* xvec = (const float*)d_in[1];
    const float* fc0w = (const float*)d_in[2];
    const float* fc0b = (const float*)d_in[3];
    const float* fc1w = (const float*)d_in[4];
    const float* p0w  = (const float*)d_in[5];
    const float* p0b  = (const float*)d_in[6];
    const float* p1w  = (const float*)d_in[7];
    const float* p1b  = (const float*)d_in[8];
    const float* bptw = (const float*)d_in[9];
    const float* bptb = (const float*)d_in[10];

    cudaFuncSetAttribute(nca_step, cudaFuncAttributeMaxDynamicSharedMemorySize, SMEM_BYTES);

    prep1<<<289, 128>>>(fc0w, fc0b, p0w, p0b, p1w, p1b);
    prep2<<<196, 256>>>(fc1w);
    init_state<<<PLANE_ / 256, 256>>>(x, xvec, bptw, bptb);
    for (int s = 0; s < STEPS_; s++)
        nca_step<<<dim3(16, 8), NT_, SMEM_BYTES>>>(s);
    final_out<<<PLANE_ / 256, 256>>>((float*)d_out);
}